// round 2
// baseline (speedup 1.0000x reference)
#include <cuda_runtime.h>
#include <cstdint>

#define NN      100000
#define DIM     256
#define NRELS   8
#define EPR     160000

#define TM 64
#define KB 32
#define APAD 4
#define BPAD 8

// Scratch for normalized int32 indices (metadata may be int32 or int64 — detected at runtime)
__device__ int g_src32[NRELS * EPR];
__device__ int g_dst32[NRELS * EPR];
__device__ int g_idx_is_i32;

__device__ __forceinline__ unsigned f2tf(float v) {
    unsigned r;
    asm("cvt.rna.tf32.f32 %0, %1;" : "=r"(r) : "f"(v));
    return r;
}

__device__ __forceinline__ void mma_tf32(float c[4], const unsigned a[4], const unsigned b[2]) {
    asm volatile(
        "mma.sync.aligned.m16n8k8.row.col.f32.tf32.tf32.f32 "
        "{%0,%1,%2,%3}, {%4,%5,%6,%7}, {%8,%9}, {%0,%1,%2,%3};\n"
        : "+f"(c[0]), "+f"(c[1]), "+f"(c[2]), "+f"(c[3])
        : "r"(a[0]), "r"(a[1]), "r"(a[2]), "r"(a[3]), "r"(b[0]), "r"(b[1]));
}

// ---------------------------------------------------------------------------
// Index dtype detection: if the buffer really holds int64 indices, every int64
// value is in [0, NN). If it holds int32, the int64 reinterpretation pairs two
// uniform-random values in [0,100000) -> virtually always >= NN somewhere.
// ---------------------------------------------------------------------------
__global__ void detect_idx_kernel(const void* srcbuf) {
    const long long* p = (const long long*)srcbuf;
    int tid = threadIdx.x;
    int bad = 0;
    #pragma unroll
    for (int i = 0; i < 4; i++) {
        long long v = p[tid * 4 + i];
        if (v < 0 || v >= NN) bad = 1;
    }
    int any = __syncthreads_or(bad);
    if (tid == 0) g_idx_is_i32 = any;   // any out-of-range -> data is int32
}

__global__ void convert_idx_kernel(const void* srcbuf, const void* dstbuf) {
    long long i = (long long)blockIdx.x * blockDim.x + threadIdx.x;
    if (i >= (long long)NRELS * EPR) return;
    if (g_idx_is_i32) {
        g_src32[i] = ((const int*)srcbuf)[i];
        g_dst32[i] = ((const int*)dstbuf)[i];
    } else {
        g_src32[i] = (int)((const long long*)srcbuf)[i];
        g_dst32[i] = (int)((const long long*)dstbuf)[i];
    }
}

// ---------------------------------------------------------------------------
// Tiled tf32 GEMM. GATHER=false: C[m,:] = X[m,:] @ W, direct store (self loop).
// GATHER=true:  per relation, C[e,:] = X[src[e],:] @ W_rel, atomicAdd to out[dst[e],:].
// Block: 256 threads = 8 warps (2x4), tile M=64 x N=256, K streamed in chunks of 32.
// ---------------------------------------------------------------------------
template<bool GATHER, bool ATOMIC>
__global__ void rgcn_gemm_kernel(const float* __restrict__ X,
                                 const float* __restrict__ W,
                                 float* __restrict__ out)
{
    __shared__ unsigned As[TM][KB + APAD];
    __shared__ unsigned Bs[KB][DIM + BPAD];
    __shared__ int sSrc[TM];
    __shared__ int sDst[TM];

    const int tid = threadIdx.x;
    const int rel = GATHER ? blockIdx.y : 0;
    const long long base = (long long)blockIdx.x * TM;

    const float* Wr = GATHER ? (W + (size_t)rel * DIM * DIM) : W;

    if (tid < TM) {
        if constexpr (GATHER) {
            long long off = (long long)rel * EPR + base + tid;
            sSrc[tid] = g_src32[off];
            sDst[tid] = g_dst32[off];
        } else {
            long long r = base + tid;
            sSrc[tid] = (r < NN) ? (int)r : 0;
            sDst[tid] = (r < NN) ? (int)r : -1;
        }
    }
    __syncthreads();

    float c[2][8][4];
    #pragma unroll
    for (int mi = 0; mi < 2; mi++)
        #pragma unroll
        for (int j = 0; j < 8; j++)
            #pragma unroll
            for (int q = 0; q < 4; q++)
                c[mi][j][q] = 0.f;

    const int warp = tid >> 5;
    const int lane = tid & 31;
    const int wm = warp >> 2;     // 0..1
    const int wn = warp & 3;      // 0..3
    const int g  = lane >> 2;     // 0..7
    const int t4 = lane & 3;      // 0..3

    const int arow  = tid >> 3;          // 0..31
    const int acol  = (tid & 7) << 2;    // 0,4,..,28
    const int brow0 = tid >> 6;          // 0..3
    const int bcol  = (tid & 63) << 2;   // 0,4,..,252

    for (int kb = 0; kb < DIM; kb += KB) {
        // ---- stage A (gathered rows of x), convert to tf32 ----
        #pragma unroll
        for (int rr = 0; rr < 2; rr++) {
            int r = arow + rr * 32;
            const float4 v = *reinterpret_cast<const float4*>(
                X + (size_t)sSrc[r] * DIM + kb + acol);
            uint4 u = make_uint4(f2tf(v.x), f2tf(v.y), f2tf(v.z), f2tf(v.w));
            *reinterpret_cast<uint4*>(&As[r][acol]) = u;
        }
        // ---- stage B (weight chunk), convert to tf32 ----
        #pragma unroll
        for (int rr = 0; rr < 8; rr++) {
            int r = brow0 + rr * 4;
            const float4 v = *reinterpret_cast<const float4*>(
                Wr + (size_t)(kb + r) * DIM + bcol);
            uint4 u = make_uint4(f2tf(v.x), f2tf(v.y), f2tf(v.z), f2tf(v.w));
            *reinterpret_cast<uint4*>(&Bs[r][bcol]) = u;
        }
        __syncthreads();

        #pragma unroll
        for (int s = 0; s < 4; s++) {
            unsigned a[2][4], b[8][2];
            #pragma unroll
            for (int mi = 0; mi < 2; mi++) {
                int rb = wm * 32 + mi * 16 + g;
                a[mi][0] = As[rb][8 * s + t4];
                a[mi][1] = As[rb + 8][8 * s + t4];
                a[mi][2] = As[rb][8 * s + t4 + 4];
                a[mi][3] = As[rb + 8][8 * s + t4 + 4];
            }
            #pragma unroll
            for (int j = 0; j < 8; j++) {
                int n = wn * 64 + j * 8 + g;
                b[j][0] = Bs[8 * s + t4][n];
                b[j][1] = Bs[8 * s + t4 + 4][n];
            }
            #pragma unroll
            for (int mi = 0; mi < 2; mi++)
                #pragma unroll
                for (int j = 0; j < 8; j++)
                    mma_tf32(c[mi][j], a[mi], b[j]);
        }
        __syncthreads();
    }

    // ---- epilogue ----
    #pragma unroll
    for (int mi = 0; mi < 2; mi++) {
        #pragma unroll
        for (int half = 0; half < 2; half++) {
            int r = wm * 32 + mi * 16 + half * 8 + g;
            int drow = sDst[r];
            if (drow < 0) continue;
            float* orow = out + (size_t)drow * DIM + wn * 64;
            #pragma unroll
            for (int j = 0; j < 8; j++) {
                int col = j * 8 + t4 * 2;
                float v0 = c[mi][j][half * 2 + 0];
                float v1 = c[mi][j][half * 2 + 1];
                if constexpr (ATOMIC) {
                    atomicAdd(orow + col,     v0);
                    atomicAdd(orow + col + 1, v1);
                } else {
                    *reinterpret_cast<float2*>(orow + col) = make_float2(v0, v1);
                }
            }
        }
    }
}

// ---------------------------------------------------------------------------
// LayerNorm over last dim (256). One warp per row.
// ---------------------------------------------------------------------------
__global__ void ln_kernel(float* __restrict__ out,
                          const float* __restrict__ gamma,
                          const float* __restrict__ beta)
{
    int row = blockIdx.x * 8 + (threadIdx.x >> 5);
    if (row >= NN) return;
    int lane = threadIdx.x & 31;
    float* p = out + (size_t)row * DIM;

    float4 v0 = *reinterpret_cast<const float4*>(p + lane * 4);
    float4 v1 = *reinterpret_cast<const float4*>(p + 128 + lane * 4);

    float s  = v0.x + v0.y + v0.z + v0.w + v1.x + v1.y + v1.z + v1.w;
    float sq = fmaf(v0.x, v0.x, fmaf(v0.y, v0.y, fmaf(v0.z, v0.z, v0.w * v0.w)))
             + fmaf(v1.x, v1.x, fmaf(v1.y, v1.y, fmaf(v1.z, v1.z, v1.w * v1.w)));

    #pragma unroll
    for (int o = 16; o; o >>= 1) {
        s  += __shfl_xor_sync(0xffffffffu, s,  o);
        sq += __shfl_xor_sync(0xffffffffu, sq, o);
    }

    float mean = s * (1.f / 256.f);
    float var  = sq * (1.f / 256.f) - mean * mean;
    float rs   = rsqrtf(var + 1e-5f);

    float4 g0 = *reinterpret_cast<const float4*>(gamma + lane * 4);
    float4 g1 = *reinterpret_cast<const float4*>(gamma + 128 + lane * 4);
    float4 b0 = *reinterpret_cast<const float4*>(beta + lane * 4);
    float4 b1 = *reinterpret_cast<const float4*>(beta + 128 + lane * 4);

    v0.x = (v0.x - mean) * rs * g0.x + b0.x;
    v0.y = (v0.y - mean) * rs * g0.y + b0.y;
    v0.z = (v0.z - mean) * rs * g0.z + b0.z;
    v0.w = (v0.w - mean) * rs * g0.w + b0.w;
    v1.x = (v1.x - mean) * rs * g1.x + b1.x;
    v1.y = (v1.y - mean) * rs * g1.y + b1.y;
    v1.z = (v1.z - mean) * rs * g1.z + b1.z;
    v1.w = (v1.w - mean) * rs * g1.w + b1.w;

    *reinterpret_cast<float4*>(p + lane * 4)       = v0;
    *reinterpret_cast<float4*>(p + 128 + lane * 4) = v1;
}

extern "C" void kernel_launch(void* const* d_in, const int* in_sizes, int n_in,
                              void* d_out, int out_size)
{
    const float* x     = (const float*)d_in[0];
    const void*  srcb  = d_in[1];
    const void*  dstb  = d_in[2];
    const float* Wself = (const float*)d_in[3];
    const float* Wrel  = (const float*)d_in[4];
    const float* gamma = (const float*)d_in[5];
    const float* beta  = (const float*)d_in[6];
    float* out = (float*)d_out;

    // Normalize indices to int32 scratch (handles int32 or int64 input dtype)
    detect_idx_kernel<<<1, 256>>>(srcb);
    {
        long long total = (long long)NRELS * EPR;
        int blocks = (int)((total + 255) / 256);
        convert_idx_kernel<<<blocks, 256>>>(srcb, dstb);
    }

    // 1) self loop: out = x @ W_self  (initializes all of out)
    rgcn_gemm_kernel<false, false><<<(NN + TM - 1) / TM, 256>>>(x, Wself, out);

    // 2) fused gather -> tf32 GEMM -> atomic scatter for all relations
    rgcn_gemm_kernel<true, true><<<dim3(EPR / TM, NRELS), 256>>>(x, Wrel, out);

    // 3) LayerNorm
    ln_kernel<<<(NN + 7) / 8, 256>>>(out, gamma, beta);
}

// round 5
// speedup vs baseline: 1.0034x; 1.0034x over previous
#include <cuda_runtime.h>
#include <cstdint>

#define NN      100000
#define DIM     256
#define NRELS   8
#define EPR     160000

#define TM 64
#define KB 32
#define APAD 4
#define BPAD 8

// Scratch for normalized int32 indices (metadata may be int32 or int64 — detected at runtime)
__device__ int g_src32[NRELS * EPR];
__device__ int g_dst32[NRELS * EPR];
__device__ int g_idx_is_i32;

__device__ __forceinline__ unsigned f2tf(float v) {
    unsigned r;
    asm("cvt.rna.tf32.f32 %0, %1;" : "=r"(r) : "f"(v));
    return r;
}

__device__ __forceinline__ void mma_tf32(float c[4], const unsigned a[4], const unsigned b[2]) {
    asm volatile(
        "mma.sync.aligned.m16n8k8.row.col.f32.tf32.tf32.f32 "
        "{%0,%1,%2,%3}, {%4,%5,%6,%7}, {%8,%9}, {%0,%1,%2,%3};\n"
        : "+f"(c[0]), "+f"(c[1]), "+f"(c[2]), "+f"(c[3])
        : "r"(a[0]), "r"(a[1]), "r"(a[2]), "r"(a[3]), "r"(b[0]), "r"(b[1]));
}

__device__ __forceinline__ void red_v4(float* addr, float v0, float v1, float v2, float v3) {
    asm volatile("red.global.add.v4.f32 [%0], {%1, %2, %3, %4};"
                 :: "l"(addr), "f"(v0), "f"(v1), "f"(v2), "f"(v3) : "memory");
}

// ---------------------------------------------------------------------------
// Index dtype detection
// ---------------------------------------------------------------------------
__global__ void detect_idx_kernel(const void* srcbuf) {
    const long long* p = (const long long*)srcbuf;
    int tid = threadIdx.x;
    int bad = 0;
    #pragma unroll
    for (int i = 0; i < 4; i++) {
        long long v = p[tid * 4 + i];
        if (v < 0 || v >= NN) bad = 1;
    }
    int any = __syncthreads_or(bad);
    if (tid == 0) g_idx_is_i32 = any;   // any out-of-range -> data is int32
}

__global__ void convert_idx_kernel(const void* srcbuf, const void* dstbuf) {
    long long i = (long long)blockIdx.x * blockDim.x + threadIdx.x;
    if (i >= (long long)NRELS * EPR) return;
    if (g_idx_is_i32) {
        g_src32[i] = ((const int*)srcbuf)[i];
        g_dst32[i] = ((const int*)dstbuf)[i];
    } else {
        g_src32[i] = (int)((const long long*)srcbuf)[i];
        g_dst32[i] = (int)((const long long*)dstbuf)[i];
    }
}

// ---------------------------------------------------------------------------
// Tiled tf32 GEMM. GATHER=false: C[m,:] = X[m,:] @ W, direct store (self loop).
// GATHER=true:  per relation, C[e,:] = X[src[e],:] @ W_rel, red.v4 scatter to out[dst[e],:].
// Block: 256 threads = 8 warps (2x4), tile M=64 x N=256, K streamed in chunks of 32.
// ---------------------------------------------------------------------------
template<bool GATHER, bool ATOMIC>
__global__ void rgcn_gemm_kernel(const float* __restrict__ X,
                                 const float* __restrict__ W,
                                 float* __restrict__ out)
{
    __shared__ unsigned As[TM][KB + APAD];
    __shared__ unsigned Bs[KB][DIM + BPAD];
    __shared__ int sSrc[TM];
    __shared__ int sDst[TM];

    const int tid = threadIdx.x;
    const int rel = GATHER ? blockIdx.y : 0;
    const long long base = (long long)blockIdx.x * TM;

    const float* Wr = GATHER ? (W + (size_t)rel * DIM * DIM) : W;

    if (tid < TM) {
        if constexpr (GATHER) {
            long long off = (long long)rel * EPR + base + tid;
            sSrc[tid] = g_src32[off];
            sDst[tid] = g_dst32[off];
        } else {
            long long r = base + tid;
            sSrc[tid] = (r < NN) ? (int)r : 0;
            sDst[tid] = (r < NN) ? (int)r : -1;
        }
    }
    __syncthreads();

    float c[2][8][4];
    #pragma unroll
    for (int mi = 0; mi < 2; mi++)
        #pragma unroll
        for (int j = 0; j < 8; j++)
            #pragma unroll
            for (int q = 0; q < 4; q++)
                c[mi][j][q] = 0.f;

    const int warp = tid >> 5;
    const int lane = tid & 31;
    const int wm = warp >> 2;     // 0..1
    const int wn = warp & 3;      // 0..3
    const int g  = lane >> 2;     // 0..7
    const int t4 = lane & 3;      // 0..3

    const int arow  = tid >> 3;          // 0..31
    const int acol  = (tid & 7) << 2;    // 0,4,..,28
    const int brow0 = tid >> 6;          // 0..3
    const int bcol  = (tid & 63) << 2;   // 0,4,..,252

    for (int kb = 0; kb < DIM; kb += KB) {
        // ---- stage A (gathered rows of x), convert to tf32 ----
        #pragma unroll
        for (int rr = 0; rr < 2; rr++) {
            int r = arow + rr * 32;
            const float4 v = *reinterpret_cast<const float4*>(
                X + (size_t)sSrc[r] * DIM + kb + acol);
            uint4 u = make_uint4(f2tf(v.x), f2tf(v.y), f2tf(v.z), f2tf(v.w));
            *reinterpret_cast<uint4*>(&As[r][acol]) = u;
        }
        // ---- stage B (weight chunk), convert to tf32 ----
        #pragma unroll
        for (int rr = 0; rr < 8; rr++) {
            int r = brow0 + rr * 4;
            const float4 v = *reinterpret_cast<const float4*>(
                Wr + (size_t)(kb + r) * DIM + bcol);
            uint4 u = make_uint4(f2tf(v.x), f2tf(v.y), f2tf(v.z), f2tf(v.w));
            *reinterpret_cast<uint4*>(&Bs[r][bcol]) = u;
        }
        __syncthreads();

        #pragma unroll
        for (int s = 0; s < 4; s++) {
            unsigned a[2][4], b[8][2];
            #pragma unroll
            for (int mi = 0; mi < 2; mi++) {
                int rb = wm * 32 + mi * 16 + g;
                a[mi][0] = As[rb][8 * s + t4];
                a[mi][1] = As[rb + 8][8 * s + t4];
                a[mi][2] = As[rb][8 * s + t4 + 4];
                a[mi][3] = As[rb + 8][8 * s + t4 + 4];
            }
            #pragma unroll
            for (int j = 0; j < 8; j++) {
                int n = wn * 64 + j * 8 + g;
                b[j][0] = Bs[8 * s + t4][n];
                b[j][1] = Bs[8 * s + t4 + 4][n];
            }
            #pragma unroll
            for (int mi = 0; mi < 2; mi++)
                #pragma unroll
                for (int j = 0; j < 8; j++)
                    mma_tf32(c[mi][j], a[mi], b[j]);
        }
        __syncthreads();
    }

    // ---- epilogue ----
    if constexpr (ATOMIC) {
        // Pair-exchange so each lane owns a contiguous float4 of one row, then
        // one red.global.add.v4.f32 per lane per (mi,j) tile. 4x fewer atomic
        // instructions, 16B per L2-atomic transaction instead of 4B.
        const bool odd = (lane & 1);
        const int colbase = wn * 64 + ((t4 & ~1) << 1);   // 16B-aligned column
        #pragma unroll
        for (int mi = 0; mi < 2; mi++) {
            // row this lane will own after the exchange
            int rowsel = wm * 32 + mi * 16 + (odd ? 8 : 0) + g;
            int drow = sDst[rowsel];
            float* addr = out + (size_t)drow * DIM + colbase;
            #pragma unroll
            for (int j = 0; j < 8; j++) {
                float s0 = __shfl_xor_sync(0xffffffffu, odd ? c[mi][j][0] : c[mi][j][2], 1);
                float s1 = __shfl_xor_sync(0xffffffffu, odd ? c[mi][j][1] : c[mi][j][3], 1);
                float v0, v1, v2, v3;
                if (!odd) { v0 = c[mi][j][0]; v1 = c[mi][j][1]; v2 = s0; v3 = s1; }
                else      { v0 = s0;          v1 = s1;          v2 = c[mi][j][2]; v3 = c[mi][j][3]; }
                red_v4(addr + j * 8, v0, v1, v2, v3);
            }
        }
    } else {
        #pragma unroll
        for (int mi = 0; mi < 2; mi++) {
            #pragma unroll
            for (int half = 0; half < 2; half++) {
                int r = wm * 32 + mi * 16 + half * 8 + g;
                int drow = sDst[r];
                if (drow < 0) continue;
                float* orow = out + (size_t)drow * DIM + wn * 64;
                #pragma unroll
                for (int j = 0; j < 8; j++) {
                    int col = j * 8 + t4 * 2;
                    float v0 = c[mi][j][half * 2 + 0];
                    float v1 = c[mi][j][half * 2 + 1];
                    *reinterpret_cast<float2*>(orow + col) = make_float2(v0, v1);
                }
            }
        }
    }
}

// ---------------------------------------------------------------------------
// LayerNorm over last dim (256). One warp per row.
// ---------------------------------------------------------------------------
__global__ void ln_kernel(float* __restrict__ out,
                          const float* __restrict__ gamma,
                          const float* __restrict__ beta)
{
    int row = blockIdx.x * 8 + (threadIdx.x >> 5);
    if (row >= NN) return;
    int lane = threadIdx.x & 31;
    float* p = out + (size_t)row * DIM;

    float4 v0 = *reinterpret_cast<const float4*>(p + lane * 4);
    float4 v1 = *reinterpret_cast<const float4*>(p + 128 + lane * 4);

    float s  = v0.x + v0.y + v0.z + v0.w + v1.x + v1.y + v1.z + v1.w;
    float sq = fmaf(v0.x, v0.x, fmaf(v0.y, v0.y, fmaf(v0.z, v0.z, v0.w * v0.w)))
             + fmaf(v1.x, v1.x, fmaf(v1.y, v1.y, fmaf(v1.z, v1.z, v1.w * v1.w)));

    #pragma unroll
    for (int o = 16; o; o >>= 1) {
        s  += __shfl_xor_sync(0xffffffffu, s,  o);
        sq += __shfl_xor_sync(0xffffffffu, sq, o);
    }

    float mean = s * (1.f / 256.f);
    float var  = sq * (1.f / 256.f) - mean * mean;
    float rs   = rsqrtf(var + 1e-5f);

    float4 g0 = *reinterpret_cast<const float4*>(gamma + lane * 4);
    float4 g1 = *reinterpret_cast<const float4*>(gamma + 128 + lane * 4);
    float4 b0 = *reinterpret_cast<const float4*>(beta + lane * 4);
    float4 b1 = *reinterpret_cast<const float4*>(beta + 128 + lane * 4);

    v0.x = (v0.x - mean) * rs * g0.x + b0.x;
    v0.y = (v0.y - mean) * rs * g0.y + b0.y;
    v0.z = (v0.z - mean) * rs * g0.z + b0.z;
    v0.w = (v0.w - mean) * rs * g0.w + b0.w;
    v1.x = (v1.x - mean) * rs * g1.x + b1.x;
    v1.y = (v1.y - mean) * rs * g1.y + b1.y;
    v1.z = (v1.z - mean) * rs * g1.z + b1.z;
    v1.w = (v1.w - mean) * rs * g1.w + b1.w;

    *reinterpret_cast<float4*>(p + lane * 4)       = v0;
    *reinterpret_cast<float4*>(p + 128 + lane * 4) = v1;
}

extern "C" void kernel_launch(void* const* d_in, const int* in_sizes, int n_in,
                              void* d_out, int out_size)
{
    const float* x     = (const float*)d_in[0];
    const void*  srcb  = d_in[1];
    const void*  dstb  = d_in[2];
    const float* Wself = (const float*)d_in[3];
    const float* Wrel  = (const float*)d_in[4];
    const float* gamma = (const float*)d_in[5];
    const float* beta  = (const float*)d_in[6];
    float* out = (float*)d_out;

    // Normalize indices to int32 scratch (handles int32 or int64 input dtype)
    detect_idx_kernel<<<1, 256>>>(srcb);
    {
        long long total = (long long)NRELS * EPR;
        int blocks = (int)((total + 255) / 256);
        convert_idx_kernel<<<blocks, 256>>>(srcb, dstb);
    }

    // 1) self loop: out = x @ W_self  (initializes all of out)
    rgcn_gemm_kernel<false, false><<<(NN + TM - 1) / TM, 256>>>(x, Wself, out);

    // 2) fused gather -> tf32 GEMM -> red.v4 scatter for all relations
    rgcn_gemm_kernel<true, true><<<dim3(EPR / TM, NRELS), 256>>>(x, Wrel, out);

    // 3) LayerNorm
    ln_kernel<<<(NN + 7) / 8, 256>>>(out, gamma, beta);
}